// round 7
// baseline (speedup 1.0000x reference)
#include <cuda_runtime.h>
#include <cuda_bf16.h>

#define NMASKS 128
#define W      1024
#define TILE_ROWS 62
#define TILES_PER_MASK 17                    // 16 x 62 rows + 1 x 32 rows
#define NTILES (NMASKS * TILES_PER_MASK)     // 2176
#define NPBLK  740                           // 148 SMs x 5 resident blocks
#define HALO_MAX 64                          // 62 + 2 -> 8 pack iters/warp
#define STRIDE 35                            // gcd(35,32)=1 -> conflict-free

__device__ unsigned g_mA[NMASKS];            // zero-init; reset by last block
__device__ unsigned g_mC[NMASKS];
__device__ unsigned g_mP[NMASKS];
__device__ unsigned g_ticket = 0;            // reset by last block each launch
__device__ unsigned g_done = 0;              // atomicInc wrap -> self-resetting

__device__ __forceinline__ void csa(unsigned a, unsigned b, unsigned c,
                                    unsigned &s, unsigned &cy) {
    unsigned t = a ^ b;
    s  = t ^ c;
    cy = (a & b) | (t & c);
}

// pack one halo row k (batched 8xLDG.128 then ballots)
__device__ __forceinline__ void pack_row_full(unsigned (*buf)[STRIDE],
                                              const float4* __restrict__ base,
                                              int r0, int k, int lane) {
    int gr = r0 - 1 + k;
    if ((unsigned)gr >= (unsigned)W) {
        buf[k][lane] = 0u;
    } else {
        const float4* __restrict__ rowp = base + (size_t)gr * (W / 4);
        float4 v[8];
        #pragma unroll
        for (int it = 0; it < 8; it++) v[it] = rowp[it * 32 + lane];
        #pragma unroll
        for (int it = 0; it < 8; it++) {
            unsigned p0 = __ballot_sync(0xffffffffu, v[it].x > 0.0f);
            unsigned p1 = __ballot_sync(0xffffffffu, v[it].y > 0.0f);
            unsigned p2 = __ballot_sync(0xffffffffu, v[it].z > 0.0f);
            unsigned p3 = __ballot_sync(0xffffffffu, v[it].w > 0.0f);
            unsigned mine = (lane == 0) ? p0 : (lane == 1) ? p1
                          : (lane == 2) ? p2 : p3;
            if (lane < 4) buf[k][1 + 4 * it + lane] = mine;
        }
    }
}

__global__ __launch_bounds__(256, 5)
void prior_kernel(const float* __restrict__ masks, float* __restrict__ out) {
    // Interleaved-bitplane packed rows; group g occupies slots 1+4g..4+4g.
    // Guard slots 0 / 33 / 34 stay zero.
    __shared__ unsigned sbuf[2][HALO_MAX][STRIDE];
    __shared__ unsigned red[2][8][3];
    __shared__ int sTick[2];
    __shared__ int is_last;

    const int tid  = threadIdx.x;
    const int lane = tid & 31;
    const int wp   = tid >> 5;               // 8 warps

    for (int j = tid; j < 2 * HALO_MAX; j += 256) {
        unsigned (*b)[STRIDE] = sbuf[j >= HALO_MAX];
        int r = (j >= HALO_MAX) ? j - HALO_MAX : j;
        b[r][0] = 0u; b[r][33] = 0u; b[r][34] = 0u;
    }

    // ---- prologue: ticket0 + full pack, prefetch ticket1 ----
    if (tid == 0) sTick[0] = (int)atomicAdd(&g_ticket, 1u);
    __syncthreads();
    int t_cur = sTick[0];
    if (t_cur < NTILES) {
        int mask = t_cur / TILES_PER_MASK;
        int ti   = t_cur - mask * TILES_PER_MASK;
        int r0   = ti * TILE_ROWS;
        int halo = ((ti < 16) ? TILE_ROWS : (W - 16 * TILE_ROWS)) + 2;
        const float4* base = (const float4*)(masks + (size_t)mask * (size_t)(W * W));
        for (int k = wp; k < halo; k += 8) pack_row_full(sbuf[0], base, r0, k, lane);
    }
    if (tid == 0) sTick[1] = (int)atomicAdd(&g_ticket, 1u);
    __syncthreads();

    int p = 0;
    while (t_cur < NTILES) {
        const int mask = t_cur / TILES_PER_MASK;
        const int ti   = t_cur - mask * TILES_PER_MASK;
        const int rows = (ti < 16) ? TILE_ROWS : (W - 16 * TILE_ROWS);
        const int t_next = sTick[p ^ 1];

        // ---- prefetch: first half of this warp's first row of next tile ----
        int nr0 = 0, nhalo = 0, gr_pre = -1;
        const float4* nbase = (const float4*)0;
        float4 v[4];
        if (t_next < NTILES) {
            int nmask = t_next / TILES_PER_MASK;
            int nti   = t_next - nmask * TILES_PER_MASK;
            nr0   = nti * TILE_ROWS;
            nhalo = ((nti < 16) ? TILE_ROWS : (W - 16 * TILE_ROWS)) + 2;
            nbase = (const float4*)(masks + (size_t)nmask * (size_t)(W * W));
            gr_pre = nr0 - 1 + wp;
            if ((unsigned)gr_pre < (unsigned)W) {
                const float4* __restrict__ rowp = nbase + (size_t)gr_pre * (W / 4);
                #pragma unroll
                for (int it = 0; it < 4; it++) v[it] = rowp[it * 32 + lane];
            }
        }

        // ---- compute current tile from sbuf[p] (prefetch loads in flight) ----
        unsigned accA = 0, accC = 0, accP = 0;
        {
            unsigned (*buf)[STRIDE] = sbuf[p];
            const int ntasks = rows * 8;
            #pragma unroll 1
            for (int base_t = 0; base_t < ntasks; base_t += 256) {
                int id = tid + base_t;
                if (id >= ntasks) break;
                int g = id & 7;
                int r = id >> 3;
                const unsigned* __restrict__ Tr = buf[r];
                const unsigned* __restrict__ Mr = buf[r + 1];
                const unsigned* __restrict__ Br = buf[r + 2];
                int s = 1 + 4 * g;

                unsigned T[4], M[4], B[4];
                #pragma unroll
                for (int k = 0; k < 4; k++) { T[k] = Tr[s+k]; M[k] = Mr[s+k]; B[k] = Br[s+k]; }
                unsigned Tp3 = Tr[s-1], Mp3 = Mr[s-1], Bp3 = Br[s-1];
                unsigned Tn0 = Tr[s+4], Mn0 = Mr[s+4], Bn0 = Br[s+4];

                unsigned TSL = (T[3] << 1) | (Tp3 >> 31), TSR = (T[0] >> 1) | (Tn0 << 31);
                unsigned MSL = (M[3] << 1) | (Mp3 >> 31), MSR = (M[0] >> 1) | (Mn0 << 31);
                unsigned BSL = (B[3] << 1) | (Bp3 >> 31), BSR = (B[0] >> 1) | (Bn0 << 31);

                #pragma unroll
                for (int k = 0; k < 4; k++) {
                    unsigned tl = (k > 0) ? T[k-1] : TSL;
                    unsigned ml = (k > 0) ? M[k-1] : MSL;
                    unsigned bl = (k > 0) ? B[k-1] : BSL;
                    unsigned tr = (k < 3) ? T[k+1] : TSR;
                    unsigned mr = (k < 3) ? M[k+1] : MSR;
                    unsigned br = (k < 3) ? B[k+1] : BSR;
                    unsigned tt = T[k], bot = B[k], mid = M[k];

                    unsigned s1, c1, s2, c2, s3, c3;
                    csa(tl, tt, tr, s1, c1);
                    csa(ml, mr, bl, s2, c2);
                    csa(bot, br, s1, s3, c3);
                    unsigned s4 = s2 ^ s3, c4 = s2 & s3;
                    unsigned u1, v1;
                    csa(c1, c2, c3, u1, v1);
                    unsigned u2 = u1 ^ c4, v2 = u1 & c4;
                    unsigned b0 = s4, b1 = u2, b2 = v1 ^ v2, b3 = v1 & v2;

                    accA += __popc(mid);
                    unsigned conn = __popc(b0 & mid) + 2u * __popc(b1 & mid)
                                  + 4u * __popc(b2 & mid) + 8u * __popc(b3 & mid);
                    unsigned tot  = __popc(b0) + 2u * __popc(b1)
                                  + 4u * __popc(b2) + 8u * __popc(b3);
                    unsigned perim = (tot - conn)
                                   + 4u * __popc(b3 & mid)
                                   + 2u * __popc(b2 & b1 & mid)
                                   +      __popc(b2 & b0 & mid);
                    accC += conn;
                    accP += perim;
                }
            }
        }
        accA = __reduce_add_sync(0xffffffffu, accA);
        accC = __reduce_add_sync(0xffffffffu, accC);
        accP = __reduce_add_sync(0xffffffffu, accP);
        if (lane == 0) { red[p][wp][0] = accA; red[p][wp][1] = accC; red[p][wp][2] = accP; }

        // ---- pack next tile into sbuf[p^1] ----
        if (t_next < NTILES) {
            unsigned (*nb)[STRIDE] = sbuf[p ^ 1];
            int k = wp;   // first row: first half prefetched
            if ((unsigned)gr_pre >= (unsigned)W) {
                nb[k][lane] = 0u;
            } else {
                const float4* __restrict__ rowp = nbase + (size_t)gr_pre * (W / 4);
                float4 w[4];
                #pragma unroll
                for (int it = 0; it < 4; it++) w[it] = rowp[(it + 4) * 32 + lane];
                #pragma unroll
                for (int it = 0; it < 4; it++) {
                    unsigned p0 = __ballot_sync(0xffffffffu, v[it].x > 0.0f);
                    unsigned p1 = __ballot_sync(0xffffffffu, v[it].y > 0.0f);
                    unsigned p2 = __ballot_sync(0xffffffffu, v[it].z > 0.0f);
                    unsigned p3 = __ballot_sync(0xffffffffu, v[it].w > 0.0f);
                    unsigned mine = (lane == 0) ? p0 : (lane == 1) ? p1
                                  : (lane == 2) ? p2 : p3;
                    if (lane < 4) nb[k][1 + 4 * it + lane] = mine;
                }
                #pragma unroll
                for (int it = 0; it < 4; it++) {
                    unsigned p0 = __ballot_sync(0xffffffffu, w[it].x > 0.0f);
                    unsigned p1 = __ballot_sync(0xffffffffu, w[it].y > 0.0f);
                    unsigned p2 = __ballot_sync(0xffffffffu, w[it].z > 0.0f);
                    unsigned p3 = __ballot_sync(0xffffffffu, w[it].w > 0.0f);
                    unsigned mine = (lane == 0) ? p0 : (lane == 1) ? p1
                                  : (lane == 2) ? p2 : p3;
                    if (lane < 4) nb[k][1 + 4 * (it + 4) + lane] = mine;
                }
            }
            for (k = wp + 8; k < nhalo; k += 8) pack_row_full(nb, nbase, nr0, k, lane);
        }

        if (tid == 0) sTick[p] = (int)atomicAdd(&g_ticket, 1u);
        __syncthreads();   // single sync: publishes red[p], sbuf[p^1], sTick[p]

        if (tid == 0) {
            unsigned a = 0, c = 0, q = 0;
            #pragma unroll
            for (int w2 = 0; w2 < 8; w2++) {
                a += red[p][w2][0]; c += red[p][w2][1]; q += red[p][w2][2];
            }
            atomicAdd(&g_mA[mask], a);
            atomicAdd(&g_mC[mask], c);
            atomicAdd(&g_mP[mask], q);
        }
        t_cur = t_next;
        p ^= 1;
    }

    // ---- completion: last finisher scores + resets state for graph replay ----
    if (tid == 0) {
        __threadfence();
        unsigned done = atomicInc(&g_done, NPBLK - 1);   // wraps to 0 itself
        is_last = (done == NPBLK - 1);
    }
    __syncthreads();

    if (is_last) {
        if (tid < NMASKS) {
            unsigned a = *(volatile unsigned*)&g_mA[tid];
            unsigned c = *(volatile unsigned*)&g_mC[tid];
            unsigned pm = *(volatile unsigned*)&g_mP[tid];

            float area  = (float)a;
            float conn  = (float)c;
            float perim = (float)pm;

            float safe_area  = (area > 0.0f) ? area : 1.0f;
            float area_ratio = area / (float)(W * W);
            float area_score = (area_ratio >= 0.001f && area_ratio <= 0.5f) ? 1.0f : 0.1f;

            float comp_score = (conn > 0.0f)
                ? fminf(1.0f, 10.0f / (conn / safe_area + 1e-6f))
                : 0.1f;

            float par = perim / safe_area;
            float shape_score = (area > 0.0f)
                ? ((par <= 100.0f) ? 1.0f : fmaxf(0.1f, 100.0f / (par + 1e-6f)))
                : 0.1f;

            float validity = 0.4f * area_score + 0.3f * comp_score + 0.3f * shape_score;
            out[tid] = fmaxf(0.05f, validity);

            g_mA[tid] = 0u; g_mC[tid] = 0u; g_mP[tid] = 0u;
        }
        if (tid == 0) g_ticket = 0u;
    }
}

extern "C" void kernel_launch(void* const* d_in, const int* in_sizes, int n_in,
                              void* d_out, int out_size) {
    const float* masks = (const float*)d_in[0];
    float* out = (float*)d_out;
    (void)in_sizes; (void)n_in; (void)out_size;

    prior_kernel<<<NPBLK, 256>>>(masks, out);
}